// round 5
// baseline (speedup 1.0000x reference)
#include <cuda_runtime.h>
#include <math.h>

// Problem constants
#define BB 8
#define NN_ 2048
#define DD 512

static const float SCALE = 0.044194173824159216f; // 1/sqrt(512)

// Scratch (device globals: allocation-free per harness rules)
__device__ float g_q[(size_t)BB * NN_ * DD];          // 32 MB
__device__ float g_k[(size_t)BB * NN_ * DD];          // 32 MB
__device__ float g_v[(size_t)BB * NN_ * DD];          // 32 MB
__device__ float g_p[(size_t)BB * NN_ * NN_];         // 128 MB scores/probs
__device__ float g_vpart[(size_t)BB * 8 * DD];        // partial V column sums

// ---------------------------------------------------------------------------
// Dtype-agnostic event_lengths decoder. Reference dtype is int64, but the
// harness may materialize integers as int32. Values are in [1, 2048], so:
//   int64 layout (little-endian): word[1] == high word of value 0 == 0
//   int32 layout:                 word[1] == event_lengths[1] >= 1
// ---------------------------------------------------------------------------
__device__ __forceinline__ int get_len(const int* __restrict__ w, int b)
{
    return (w[1] == 0) ? w[2 * b] : w[b];
}

// ---------------------------------------------------------------------------
// Kernel 1: fused QKV projection.  out[m,e] = sum_d x[m,d]*W[e,d] + bias[e]
// NT GEMM, M=16384, N=512, K=512. 128x128 CTA tile, 8x8 microtile, BK=8.
// ---------------------------------------------------------------------------
__global__ __launch_bounds__(256)
void qkv_gemm(const float* __restrict__ x,
              const float* __restrict__ Wq, const float* __restrict__ bq,
              const float* __restrict__ Wk, const float* __restrict__ bk,
              const float* __restrict__ Wv, const float* __restrict__ bv)
{
    const int mat = blockIdx.z;
    const float* __restrict__ W    = (mat == 0) ? Wq : (mat == 1) ? Wk : Wv;
    const float* __restrict__ bias = (mat == 0) ? bq : (mat == 1) ? bk : bv;
    float* out = (mat == 0) ? g_q : (mat == 1) ? g_k : g_v;

    __shared__ __align__(16) float As[8][128];
    __shared__ __align__(16) float Bs[8][128];

    const int tid = threadIdx.x;
    const int tx = tid & 15;
    const int ty = tid >> 4;
    const int m0 = blockIdx.x * 128;
    const int e0 = blockIdx.y * 128;

    const int lRow = tid >> 1;
    const int lK4  = (tid & 1) * 4;

    const float* aPtr = x + (size_t)(m0 + lRow) * DD + lK4;
    const float* bPtr = W + (size_t)(e0 + lRow) * DD + lK4;

    float acc[8][8];
    #pragma unroll
    for (int i = 0; i < 8; ++i)
        #pragma unroll
        for (int j = 0; j < 8; ++j) acc[i][j] = 0.f;

    for (int k0 = 0; k0 < DD; k0 += 8) {
        float4 av  = *(const float4*)(aPtr + k0);
        float4 bv4 = *(const float4*)(bPtr + k0);
        __syncthreads();
        As[lK4 + 0][lRow] = av.x;  As[lK4 + 1][lRow] = av.y;
        As[lK4 + 2][lRow] = av.z;  As[lK4 + 3][lRow] = av.w;
        Bs[lK4 + 0][lRow] = bv4.x; Bs[lK4 + 1][lRow] = bv4.y;
        Bs[lK4 + 2][lRow] = bv4.z; Bs[lK4 + 3][lRow] = bv4.w;
        __syncthreads();
        #pragma unroll
        for (int k = 0; k < 8; ++k) {
            float a[8], b[8];
            #pragma unroll
            for (int i = 0; i < 8; ++i) a[i] = As[k][ty * 8 + i];
            #pragma unroll
            for (int j = 0; j < 8; ++j) b[j] = Bs[k][tx * 8 + j];
            #pragma unroll
            for (int i = 0; i < 8; ++i)
                #pragma unroll
                for (int j = 0; j < 8; ++j)
                    acc[i][j] += a[i] * b[j];
        }
    }

    float bb[8];
    #pragma unroll
    for (int j = 0; j < 8; ++j) bb[j] = bias[e0 + tx * 8 + j];

    #pragma unroll
    for (int i = 0; i < 8; ++i) {
        const int row = m0 + ty * 8 + i;
        float* orow = out + (size_t)row * DD + e0 + tx * 8;
        #pragma unroll
        for (int j = 0; j < 8; ++j)
            orow[j] = acc[i][j] + bb[j];
    }
}

// ---------------------------------------------------------------------------
// Kernel 2: scores[b,i,j] = scale * dot(q[b,i], k[b,j]).  NT GEMM, K=512.
// Per-tile early exit on event length L (only i<L and j<L matter).
// ---------------------------------------------------------------------------
__global__ __launch_bounds__(256)
void score_gemm(const int* __restrict__ lens)
{
    const int b  = blockIdx.z;
    const int L  = get_len(lens, b);
    const int i0 = blockIdx.x * 128;
    const int j0 = blockIdx.y * 128;
    if (i0 >= L || j0 >= L) return;

    const float* __restrict__ q  = g_q + (size_t)b * NN_ * DD;
    const float* __restrict__ kk = g_k + (size_t)b * NN_ * DD;
    float* p = g_p + (size_t)b * NN_ * NN_;

    __shared__ __align__(16) float As[8][128];
    __shared__ __align__(16) float Bs[8][128];

    const int tid = threadIdx.x;
    const int tx = tid & 15;
    const int ty = tid >> 4;
    const int lRow = tid >> 1;
    const int lK4  = (tid & 1) * 4;

    const float* aPtr = q  + (size_t)(i0 + lRow) * DD + lK4;
    const float* bPtr = kk + (size_t)(j0 + lRow) * DD + lK4;

    float acc[8][8];
    #pragma unroll
    for (int i = 0; i < 8; ++i)
        #pragma unroll
        for (int j = 0; j < 8; ++j) acc[i][j] = 0.f;

    for (int k0 = 0; k0 < DD; k0 += 8) {
        float4 av  = *(const float4*)(aPtr + k0);
        float4 bv4 = *(const float4*)(bPtr + k0);
        __syncthreads();
        As[lK4 + 0][lRow] = av.x;  As[lK4 + 1][lRow] = av.y;
        As[lK4 + 2][lRow] = av.z;  As[lK4 + 3][lRow] = av.w;
        Bs[lK4 + 0][lRow] = bv4.x; Bs[lK4 + 1][lRow] = bv4.y;
        Bs[lK4 + 2][lRow] = bv4.z; Bs[lK4 + 3][lRow] = bv4.w;
        __syncthreads();
        #pragma unroll
        for (int k = 0; k < 8; ++k) {
            float a[8], b2[8];
            #pragma unroll
            for (int i = 0; i < 8; ++i) a[i] = As[k][ty * 8 + i];
            #pragma unroll
            for (int j = 0; j < 8; ++j) b2[j] = Bs[k][tx * 8 + j];
            #pragma unroll
            for (int i = 0; i < 8; ++i)
                #pragma unroll
                for (int j = 0; j < 8; ++j)
                    acc[i][j] += a[i] * b2[j];
        }
    }

    #pragma unroll
    for (int i = 0; i < 8; ++i) {
        const int row = i0 + ty * 8 + i;
        float* prow = p + (size_t)row * NN_ + j0 + tx * 8;
        #pragma unroll
        for (int j = 0; j < 8; ++j)
            prow[j] = acc[i][j] * SCALE;
    }
}

// ---------------------------------------------------------------------------
// Kernel 3: row softmax over keys j<L, in place. One block per (b, i).
// ---------------------------------------------------------------------------
__device__ __forceinline__ float blockReduceMax(float v, float* red)
{
    #pragma unroll
    for (int o = 16; o; o >>= 1) v = fmaxf(v, __shfl_xor_sync(0xffffffffu, v, o));
    const int tid = threadIdx.x;
    if ((tid & 31) == 0) red[tid >> 5] = v;
    __syncthreads();
    float r = red[0];
    #pragma unroll
    for (int w = 1; w < 8; ++w) r = fmaxf(r, red[w]);
    __syncthreads();
    return r;
}

__device__ __forceinline__ float blockReduceSum(float v, float* red)
{
    #pragma unroll
    for (int o = 16; o; o >>= 1) v += __shfl_xor_sync(0xffffffffu, v, o);
    const int tid = threadIdx.x;
    if ((tid & 31) == 0) red[tid >> 5] = v;
    __syncthreads();
    float r = red[0];
    #pragma unroll
    for (int w = 1; w < 8; ++w) r += red[w];
    __syncthreads();
    return r;
}

__global__ __launch_bounds__(256)
void softmax_kernel(const int* __restrict__ lens)
{
    const int b = blockIdx.y;
    const int i = blockIdx.x;
    const int L = get_len(lens, b);
    if (i >= L) return;

    float* row = g_p + (size_t)b * NN_ * NN_ + (size_t)i * NN_;
    const int tid = threadIdx.x;
    __shared__ float red[8];

    float mx = -3.0e38f;
    for (int j = tid; j < L; j += 256) mx = fmaxf(mx, row[j]);
    mx = blockReduceMax(mx, red);

    float s = 0.f;
    for (int j = tid; j < L; j += 256) {
        float e = __expf(row[j] - mx);
        row[j] = e;
        s += e;
    }
    s = blockReduceSum(s, red);
    const float inv = 1.0f / s;

    for (int j = tid; j < L; j += 256) row[j] *= inv;
}

// ---------------------------------------------------------------------------
// Kernel 4: out[b,i,d] = sum_{j<L} P[b,i,j] * v[b,j,d].  NN GEMM, K=L dynamic.
// Stores only rows i<L (rows i>=L are filled by the tail kernels).
// ---------------------------------------------------------------------------
__global__ __launch_bounds__(256)
void out_gemm(const int* __restrict__ lens, float* __restrict__ out)
{
    const int b  = blockIdx.z;
    const int L  = get_len(lens, b);
    const int i0 = blockIdx.x * 128;
    if (i0 >= L) return;
    const int d0 = blockIdx.y * 128;

    const float* __restrict__ p = g_p + (size_t)b * NN_ * NN_;
    const float* __restrict__ v = g_v + (size_t)b * NN_ * DD;

    __shared__ __align__(16) float As[8][128];
    __shared__ __align__(16) float Bs[8][128];

    const int tid = threadIdx.x;
    const int tx = tid & 15;
    const int ty = tid >> 4;
    const int lRow = tid >> 1;        // A: row within 128-tile
    const int lK4  = (tid & 1) * 4;   // A: k quad
    const int vRow  = tid >> 5;       // B: k row 0..7
    const int vCol4 = (tid & 31) * 4; // B: d quad

    float acc[8][8];
    #pragma unroll
    for (int i = 0; i < 8; ++i)
        #pragma unroll
        for (int j = 0; j < 8; ++j) acc[i][j] = 0.f;

    const int Kiter = (L + 7) >> 3;
    for (int t = 0; t < Kiter; ++t) {
        const int k0 = t * 8;
        const int ka = k0 + lK4;
        const float* ap = p + (size_t)(i0 + lRow) * NN_ + ka;
        float4 av;
        if (ka + 4 <= L) {
            av = *(const float4*)ap;
        } else {
            av.x = (ka + 0 < L) ? ap[0] : 0.f;
            av.y = (ka + 1 < L) ? ap[1] : 0.f;
            av.z = (ka + 2 < L) ? ap[2] : 0.f;
            av.w = (ka + 3 < L) ? ap[3] : 0.f;
        }
        const int kb = k0 + vRow;
        float4 bv4;
        if (kb < L) bv4 = *(const float4*)(v + (size_t)kb * DD + d0 + vCol4);
        else        bv4 = make_float4(0.f, 0.f, 0.f, 0.f);

        __syncthreads();
        As[lK4 + 0][lRow] = av.x; As[lK4 + 1][lRow] = av.y;
        As[lK4 + 2][lRow] = av.z; As[lK4 + 3][lRow] = av.w;
        *(float4*)&Bs[vRow][vCol4] = bv4;
        __syncthreads();

        #pragma unroll
        for (int k = 0; k < 8; ++k) {
            float a[8], b2[8];
            #pragma unroll
            for (int i = 0; i < 8; ++i) a[i] = As[k][ty * 8 + i];
            #pragma unroll
            for (int j = 0; j < 8; ++j) b2[j] = Bs[k][tx * 8 + j];
            #pragma unroll
            for (int i = 0; i < 8; ++i)
                #pragma unroll
                for (int j = 0; j < 8; ++j)
                    acc[i][j] += a[i] * b2[j];
        }
    }

    #pragma unroll
    for (int i = 0; i < 8; ++i) {
        const int row = i0 + ty * 8 + i;
        if (row < L) {
            float* orow = out + ((size_t)b * NN_ + row) * DD + d0 + tx * 8;
            #pragma unroll
            for (int j = 0; j < 8; ++j) orow[j] = acc[i][j];
        }
    }
}

// ---------------------------------------------------------------------------
// Kernel 5a: partial column sums of V (8 segments of 256 rows each).
// ---------------------------------------------------------------------------
__global__ __launch_bounds__(128)
void vmean_part()
{
    const int b   = blockIdx.y;
    const int seg = blockIdx.z;
    const int d   = blockIdx.x * 128 + threadIdx.x;
    const float* v = g_v + (size_t)b * NN_ * DD + (size_t)seg * 256 * DD + d;
    float s0 = 0.f, s1 = 0.f, s2 = 0.f, s3 = 0.f;
    for (int n = 0; n < 256; n += 4) {
        s0 += v[(size_t)(n + 0) * DD];
        s1 += v[(size_t)(n + 1) * DD];
        s2 += v[(size_t)(n + 2) * DD];
        s3 += v[(size_t)(n + 3) * DD];
    }
    g_vpart[((size_t)b * 8 + seg) * DD + d] = (s0 + s1) + (s2 + s3);
}

// ---------------------------------------------------------------------------
// Kernel 5b: rows i >= L get mean over ALL 2048 V rows (uniform softmax of a
// fully-masked row is exactly 1/N for every key, including keys >= L).
// ---------------------------------------------------------------------------
__global__ __launch_bounds__(256)
void fill_tail(const int* __restrict__ lens, float* __restrict__ out)
{
    const int b  = blockIdx.y;
    const int L  = get_len(lens, b);
    const int i0 = blockIdx.x * 128;
    const int iStart = (i0 > L) ? i0 : L;
    const int iEnd   = (i0 + 128 < NN_) ? (i0 + 128) : NN_;
    if (iStart >= iEnd) return;

    __shared__ __align__(16) float mean[DD];
    const int tid = threadIdx.x;
    for (int d = tid; d < DD; d += 256) {
        float s = 0.f;
        #pragma unroll
        for (int z = 0; z < 8; ++z) s += g_vpart[((size_t)b * 8 + z) * DD + d];
        mean[d] = s * (1.0f / (float)NN_);
    }
    __syncthreads();

    const int nRows = iEnd - iStart;
    for (int lin = tid; lin < nRows * 128; lin += 256) {
        const int r  = iStart + (lin >> 7);
        const int c4 = (lin & 127);
        const float4 m = *(const float4*)&mean[c4 * 4];
        *(float4*)&out[((size_t)b * NN_ + r) * DD + (size_t)c4 * 4] = m;
    }
}

// ---------------------------------------------------------------------------
extern "C" void kernel_launch(void* const* d_in, const int* in_sizes, int n_in,
                              void* d_out, int out_size)
{
    const float* x    = (const float*)d_in[0];
    const int*   lens = (const int*)d_in[1];   // int32 or int64 — decoded in-kernel
    const float* Wq   = (const float*)d_in[2];
    const float* bq   = (const float*)d_in[3];
    const float* Wk   = (const float*)d_in[4];
    const float* bk   = (const float*)d_in[5];
    const float* Wv   = (const float*)d_in[6];
    const float* bv   = (const float*)d_in[7];
    float* out = (float*)d_out;

    qkv_gemm<<<dim3(128, 4, 3), 256>>>(x, Wq, bq, Wk, bk, Wv, bv);
    score_gemm<<<dim3(16, 16, 8), 256>>>(lens);
    softmax_kernel<<<dim3(2048, 8), 256>>>(lens);
    out_gemm<<<dim3(16, 4, 8), 256>>>(lens, out);
    vmean_part<<<dim3(4, 8, 8), 128>>>();
    fill_tail<<<dim3(16, 8), 256>>>(lens, out);
}

// round 7
// speedup vs baseline: 1.1597x; 1.1597x over previous
#include <cuda_runtime.h>
#include <math.h>

// Problem constants
#define BB 8
#define NN_ 2048
#define DD 512

static const float SCALE = 0.044194173824159216f; // 1/sqrt(512)

typedef unsigned long long ull;

// Scratch (device globals: allocation-free per harness rules)
__device__ float g_q[(size_t)BB * NN_ * DD];          // 32 MB
__device__ float g_k[(size_t)BB * NN_ * DD];          // 32 MB
__device__ float g_v[(size_t)BB * NN_ * DD];          // 32 MB
__device__ float g_p[(size_t)BB * NN_ * NN_];         // 128 MB scores/probs
__device__ float g_vpart[(size_t)BB * 8 * DD];        // partial V column sums

// ---------------------------------------------------------------------------
// Packed fp32x2 helpers (Blackwell FFMA2 — only reachable via PTX f32x2 ops).
// Numerics identical to two scalar fmaf.
// ---------------------------------------------------------------------------
__device__ __forceinline__ void fma2(ull& d, ull a, ull b)
{
    asm("fma.rn.f32x2 %0, %1, %2, %0;" : "+l"(d) : "l"(a), "l"(b));
}
__device__ __forceinline__ ull pdup(float a)
{
    ull d; unsigned ai = __float_as_uint(a);
    asm("mov.b64 %0, {%1, %1};" : "=l"(d) : "r"(ai));
    return d;
}
__device__ __forceinline__ float2 unpack2(ull p)
{
    unsigned lo, hi;
    asm("mov.b64 {%0, %1}, %2;" : "=r"(lo), "=r"(hi) : "l"(p));
    float2 r; r.x = __uint_as_float(lo); r.y = __uint_as_float(hi);
    return r;
}

// ---------------------------------------------------------------------------
// Dtype-agnostic event_lengths decoder (int64 vs int32 materialization).
// ---------------------------------------------------------------------------
__device__ __forceinline__ int get_len(const int* __restrict__ w, int b)
{
    return (w[1] == 0) ? w[2 * b] : w[b];
}

// ---------------------------------------------------------------------------
// Shared inner product step: 8x8 microtile as 8x4 packed f32x2 FMAs.
// ---------------------------------------------------------------------------
#define MICRO_K_STEP(AsB, BsB, k)                                              \
    {                                                                          \
        const float4* pa = (const float4*)&AsB[k][ty * 8];                     \
        float4 av0 = pa[0], av1 = pa[1];                                       \
        const ulonglong2* pb = (const ulonglong2*)&BsB[k][tx * 8];             \
        ulonglong2 bq0 = pb[0], bq1 = pb[1];                                   \
        ull a2[8];                                                             \
        a2[0] = pdup(av0.x); a2[1] = pdup(av0.y);                              \
        a2[2] = pdup(av0.z); a2[3] = pdup(av0.w);                              \
        a2[4] = pdup(av1.x); a2[5] = pdup(av1.y);                              \
        a2[6] = pdup(av1.z); a2[7] = pdup(av1.w);                              \
        ull b2_0 = bq0.x, b2_1 = bq0.y, b2_2 = bq1.x, b2_3 = bq1.y;            \
        _Pragma("unroll")                                                      \
        for (int i = 0; i < 8; ++i) {                                          \
            fma2(acc[i][0], a2[i], b2_0);                                      \
            fma2(acc[i][1], a2[i], b2_1);                                      \
            fma2(acc[i][2], a2[i], b2_2);                                      \
            fma2(acc[i][3], a2[i], b2_3);                                      \
        }                                                                      \
    }

// ---------------------------------------------------------------------------
// Kernel 1: fused QKV projection (NT GEMM M=16384, N=512, K=512).
// 128x128 tile, BK=16, double-buffered smem, f32x2 FMAs.
// ---------------------------------------------------------------------------
__global__ __launch_bounds__(256, 2)
void qkv_gemm(const float* __restrict__ x,
              const float* __restrict__ Wq, const float* __restrict__ bq,
              const float* __restrict__ Wk, const float* __restrict__ bk,
              const float* __restrict__ Wv, const float* __restrict__ bv)
{
    const int mat = blockIdx.z;
    const float* __restrict__ W    = (mat == 0) ? Wq : (mat == 1) ? Wk : Wv;
    const float* __restrict__ bias = (mat == 0) ? bq : (mat == 1) ? bk : bv;
    float* out = (mat == 0) ? g_q : (mat == 1) ? g_k : g_v;

    __shared__ __align__(16) float As[2][16][128];
    __shared__ __align__(16) float Bs[2][16][128];

    const int tid = threadIdx.x;
    const int tx = tid & 15, ty = tid >> 4;
    const int m0 = blockIdx.x * 128, e0 = blockIdx.y * 128;
    const int lRow = tid >> 1, lK8 = (tid & 1) * 8;

    const float* aP = x + (size_t)(m0 + lRow) * DD + lK8;
    const float* bP = W + (size_t)(e0 + lRow) * DD + lK8;

    // Prologue: tile 0
    float4 ra0 = *(const float4*)(aP),     ra1 = *(const float4*)(aP + 4);
    float4 rb0 = *(const float4*)(bP),     rb1 = *(const float4*)(bP + 4);
    As[0][lK8+0][lRow]=ra0.x; As[0][lK8+1][lRow]=ra0.y; As[0][lK8+2][lRow]=ra0.z; As[0][lK8+3][lRow]=ra0.w;
    As[0][lK8+4][lRow]=ra1.x; As[0][lK8+5][lRow]=ra1.y; As[0][lK8+6][lRow]=ra1.z; As[0][lK8+7][lRow]=ra1.w;
    Bs[0][lK8+0][lRow]=rb0.x; Bs[0][lK8+1][lRow]=rb0.y; Bs[0][lK8+2][lRow]=rb0.z; Bs[0][lK8+3][lRow]=rb0.w;
    Bs[0][lK8+4][lRow]=rb1.x; Bs[0][lK8+5][lRow]=rb1.y; Bs[0][lK8+6][lRow]=rb1.z; Bs[0][lK8+7][lRow]=rb1.w;
    __syncthreads();

    ull acc[8][4];
    #pragma unroll
    for (int i = 0; i < 8; ++i)
        #pragma unroll
        for (int j = 0; j < 4; ++j) acc[i][j] = 0ULL;

    int buf = 0;
    const int T = DD / 16; // 32
    #pragma unroll 1
    for (int t = 0; t < T; ++t) {
        if (t + 1 < T) {
            ra0 = *(const float4*)(aP + (t + 1) * 16);
            ra1 = *(const float4*)(aP + (t + 1) * 16 + 4);
            rb0 = *(const float4*)(bP + (t + 1) * 16);
            rb1 = *(const float4*)(bP + (t + 1) * 16 + 4);
        }
        #pragma unroll
        for (int k = 0; k < 16; ++k) MICRO_K_STEP(As[buf], Bs[buf], k);
        if (t + 1 < T) {
            const int nb = buf ^ 1;
            As[nb][lK8+0][lRow]=ra0.x; As[nb][lK8+1][lRow]=ra0.y; As[nb][lK8+2][lRow]=ra0.z; As[nb][lK8+3][lRow]=ra0.w;
            As[nb][lK8+4][lRow]=ra1.x; As[nb][lK8+5][lRow]=ra1.y; As[nb][lK8+6][lRow]=ra1.z; As[nb][lK8+7][lRow]=ra1.w;
            Bs[nb][lK8+0][lRow]=rb0.x; Bs[nb][lK8+1][lRow]=rb0.y; Bs[nb][lK8+2][lRow]=rb0.z; Bs[nb][lK8+3][lRow]=rb0.w;
            Bs[nb][lK8+4][lRow]=rb1.x; Bs[nb][lK8+5][lRow]=rb1.y; Bs[nb][lK8+6][lRow]=rb1.z; Bs[nb][lK8+7][lRow]=rb1.w;
            __syncthreads();
            buf = nb;
        }
    }

    float bb[8];
    #pragma unroll
    for (int j = 0; j < 8; ++j) bb[j] = bias[e0 + tx * 8 + j];

    #pragma unroll
    for (int i = 0; i < 8; ++i) {
        const int row = m0 + ty * 8 + i;
        float* orow = out + (size_t)row * DD + e0 + tx * 8;
        float2 v0 = unpack2(acc[i][0]), v1 = unpack2(acc[i][1]);
        float2 v2 = unpack2(acc[i][2]), v3 = unpack2(acc[i][3]);
        *(float4*)(orow)     = make_float4(v0.x + bb[0], v0.y + bb[1], v1.x + bb[2], v1.y + bb[3]);
        *(float4*)(orow + 4) = make_float4(v2.x + bb[4], v2.y + bb[5], v3.x + bb[6], v3.y + bb[7]);
    }
}

// ---------------------------------------------------------------------------
// Kernel 2: scores = scale * q @ k^T (NT GEMM K=512), tile-gated on L.
// ---------------------------------------------------------------------------
__global__ __launch_bounds__(256, 2)
void score_gemm(const int* __restrict__ lens)
{
    const int b  = blockIdx.z;
    const int L  = get_len(lens, b);
    const int i0 = blockIdx.x * 128;
    const int j0 = blockIdx.y * 128;
    if (i0 >= L || j0 >= L) return;

    const float* __restrict__ q  = g_q + (size_t)b * NN_ * DD;
    const float* __restrict__ kk = g_k + (size_t)b * NN_ * DD;
    float* p = g_p + (size_t)b * NN_ * NN_;

    __shared__ __align__(16) float As[2][16][128];
    __shared__ __align__(16) float Bs[2][16][128];

    const int tid = threadIdx.x;
    const int tx = tid & 15, ty = tid >> 4;
    const int lRow = tid >> 1, lK8 = (tid & 1) * 8;

    const float* aP = q  + (size_t)(i0 + lRow) * DD + lK8;
    const float* bP = kk + (size_t)(j0 + lRow) * DD + lK8;

    float4 ra0 = *(const float4*)(aP),     ra1 = *(const float4*)(aP + 4);
    float4 rb0 = *(const float4*)(bP),     rb1 = *(const float4*)(bP + 4);
    As[0][lK8+0][lRow]=ra0.x; As[0][lK8+1][lRow]=ra0.y; As[0][lK8+2][lRow]=ra0.z; As[0][lK8+3][lRow]=ra0.w;
    As[0][lK8+4][lRow]=ra1.x; As[0][lK8+5][lRow]=ra1.y; As[0][lK8+6][lRow]=ra1.z; As[0][lK8+7][lRow]=ra1.w;
    Bs[0][lK8+0][lRow]=rb0.x; Bs[0][lK8+1][lRow]=rb0.y; Bs[0][lK8+2][lRow]=rb0.z; Bs[0][lK8+3][lRow]=rb0.w;
    Bs[0][lK8+4][lRow]=rb1.x; Bs[0][lK8+5][lRow]=rb1.y; Bs[0][lK8+6][lRow]=rb1.z; Bs[0][lK8+7][lRow]=rb1.w;
    __syncthreads();

    ull acc[8][4];
    #pragma unroll
    for (int i = 0; i < 8; ++i)
        #pragma unroll
        for (int j = 0; j < 4; ++j) acc[i][j] = 0ULL;

    int buf = 0;
    const int T = DD / 16;
    #pragma unroll 1
    for (int t = 0; t < T; ++t) {
        if (t + 1 < T) {
            ra0 = *(const float4*)(aP + (t + 1) * 16);
            ra1 = *(const float4*)(aP + (t + 1) * 16 + 4);
            rb0 = *(const float4*)(bP + (t + 1) * 16);
            rb1 = *(const float4*)(bP + (t + 1) * 16 + 4);
        }
        #pragma unroll
        for (int k = 0; k < 16; ++k) MICRO_K_STEP(As[buf], Bs[buf], k);
        if (t + 1 < T) {
            const int nb = buf ^ 1;
            As[nb][lK8+0][lRow]=ra0.x; As[nb][lK8+1][lRow]=ra0.y; As[nb][lK8+2][lRow]=ra0.z; As[nb][lK8+3][lRow]=ra0.w;
            As[nb][lK8+4][lRow]=ra1.x; As[nb][lK8+5][lRow]=ra1.y; As[nb][lK8+6][lRow]=ra1.z; As[nb][lK8+7][lRow]=ra1.w;
            Bs[nb][lK8+0][lRow]=rb0.x; Bs[nb][lK8+1][lRow]=rb0.y; Bs[nb][lK8+2][lRow]=rb0.z; Bs[nb][lK8+3][lRow]=rb0.w;
            Bs[nb][lK8+4][lRow]=rb1.x; Bs[nb][lK8+5][lRow]=rb1.y; Bs[nb][lK8+6][lRow]=rb1.z; Bs[nb][lK8+7][lRow]=rb1.w;
            __syncthreads();
            buf = nb;
        }
    }

    #pragma unroll
    for (int i = 0; i < 8; ++i) {
        const int row = i0 + ty * 8 + i;
        float* prow = p + (size_t)row * NN_ + j0 + tx * 8;
        float2 v0 = unpack2(acc[i][0]), v1 = unpack2(acc[i][1]);
        float2 v2 = unpack2(acc[i][2]), v3 = unpack2(acc[i][3]);
        *(float4*)(prow)     = make_float4(v0.x * SCALE, v0.y * SCALE, v1.x * SCALE, v1.y * SCALE);
        *(float4*)(prow + 4) = make_float4(v2.x * SCALE, v2.y * SCALE, v3.x * SCALE, v3.y * SCALE);
    }
}

// ---------------------------------------------------------------------------
// Kernel 2b: zero the prob strip cols [L, ceil16(L)) for rows < L, so
// out_gemm can run fully unpredicated over k < ceil16(L)  (p=0 kills v).
// ---------------------------------------------------------------------------
__global__ __launch_bounds__(256)
void zero_pad(const int* __restrict__ lens)
{
    const int b = blockIdx.y;
    const int L = get_len(lens, b);
    const int Lc = (L + 15) & ~15;
    const int w = Lc - L;
    if (w == 0) return;
    float* p = g_p + (size_t)b * NN_ * NN_;
    const int i0 = blockIdx.x * 128;
    for (int idx = threadIdx.x; idx < 128 * w; idx += 256) {
        const int r = i0 + idx / w;
        const int c = L + idx % w;
        if (r < L) p[(size_t)r * NN_ + c] = 0.f;
    }
}

// ---------------------------------------------------------------------------
// Kernel 3: row softmax over keys j<L, in place.
// ---------------------------------------------------------------------------
__device__ __forceinline__ float blockReduceMax(float v, float* red)
{
    #pragma unroll
    for (int o = 16; o; o >>= 1) v = fmaxf(v, __shfl_xor_sync(0xffffffffu, v, o));
    const int tid = threadIdx.x;
    if ((tid & 31) == 0) red[tid >> 5] = v;
    __syncthreads();
    float r = red[0];
    #pragma unroll
    for (int w = 1; w < 8; ++w) r = fmaxf(r, red[w]);
    __syncthreads();
    return r;
}

__device__ __forceinline__ float blockReduceSum(float v, float* red)
{
    #pragma unroll
    for (int o = 16; o; o >>= 1) v += __shfl_xor_sync(0xffffffffu, v, o);
    const int tid = threadIdx.x;
    if ((tid & 31) == 0) red[tid >> 5] = v;
    __syncthreads();
    float r = red[0];
    #pragma unroll
    for (int w = 1; w < 8; ++w) r += red[w];
    __syncthreads();
    return r;
}

__global__ __launch_bounds__(256)
void softmax_kernel(const int* __restrict__ lens)
{
    const int b = blockIdx.y;
    const int i = blockIdx.x;
    const int L = get_len(lens, b);
    if (i >= L) return;

    float* row = g_p + (size_t)b * NN_ * NN_ + (size_t)i * NN_;
    const int tid = threadIdx.x;
    __shared__ float red[8];

    float mx = -3.0e38f;
    for (int j = tid; j < L; j += 256) mx = fmaxf(mx, row[j]);
    mx = blockReduceMax(mx, red);

    float s = 0.f;
    for (int j = tid; j < L; j += 256) {
        float e = __expf(row[j] - mx);
        row[j] = e;
        s += e;
    }
    s = blockReduceSum(s, red);
    const float inv = 1.0f / s;

    for (int j = tid; j < L; j += 256) row[j] *= inv;
}

// ---------------------------------------------------------------------------
// Kernel 4: out = P @ V (NN GEMM, K = ceil16(L), fully unpredicated loads —
// the zero strip guarantees p=0 for k in [L, ceil16(L))).
// ---------------------------------------------------------------------------
__global__ __launch_bounds__(256, 2)
void out_gemm(const int* __restrict__ lens, float* __restrict__ out)
{
    const int b  = blockIdx.z;
    const int L  = get_len(lens, b);
    const int i0 = blockIdx.x * 128;
    if (i0 >= L) return;
    const int d0 = blockIdx.y * 128;

    const float* __restrict__ p = g_p + (size_t)b * NN_ * NN_;
    const float* __restrict__ v = g_v + (size_t)b * NN_ * DD;

    __shared__ __align__(16) float As[2][16][128];
    __shared__ __align__(16) float Bs[2][16][128];

    const int tid = threadIdx.x;
    const int tx = tid & 15, ty = tid >> 4;
    const int lRow = tid >> 1, lK8 = (tid & 1) * 8;      // A (P) staging
    const int vRow = tid >> 4, vCol8 = (tid & 15) * 8;   // B (V) staging

    const float* aP = p + (size_t)(i0 + lRow) * NN_ + lK8;
    const float* bP = v + (size_t)vRow * DD + d0 + vCol8;

    const int T = (L + 15) >> 4;

    float4 ra0 = *(const float4*)(aP),     ra1 = *(const float4*)(aP + 4);
    float4 rb0 = *(const float4*)(bP),     rb1 = *(const float4*)(bP + 4);
    As[0][lK8+0][lRow]=ra0.x; As[0][lK8+1][lRow]=ra0.y; As[0][lK8+2][lRow]=ra0.z; As[0][lK8+3][lRow]=ra0.w;
    As[0][lK8+4][lRow]=ra1.x; As[0][lK8+5][lRow]=ra1.y; As[0][lK8+6][lRow]=ra1.z; As[0][lK8+7][lRow]=ra1.w;
    *(float4*)&Bs[0][vRow][vCol8]     = rb0;
    *(float4*)&Bs[0][vRow][vCol8 + 4] = rb1;
    __syncthreads();

    ull acc[8][4];
    #pragma unroll
    for (int i = 0; i < 8; ++i)
        #pragma unroll
        for (int j = 0; j < 4; ++j) acc[i][j] = 0ULL;

    int buf = 0;
    #pragma unroll 1
    for (int t = 0; t < T; ++t) {
        if (t + 1 < T) {
            ra0 = *(const float4*)(aP + (t + 1) * 16);
            ra1 = *(const float4*)(aP + (t + 1) * 16 + 4);
            rb0 = *(const float4*)(bP + (size_t)(t + 1) * 16 * DD);
            rb1 = *(const float4*)(bP + (size_t)(t + 1) * 16 * DD + 4);
        }
        #pragma unroll
        for (int k = 0; k < 16; ++k) MICRO_K_STEP(As[buf], Bs[buf], k);
        if (t + 1 < T) {
            const int nb = buf ^ 1;
            As[nb][lK8+0][lRow]=ra0.x; As[nb][lK8+1][lRow]=ra0.y; As[nb][lK8+2][lRow]=ra0.z; As[nb][lK8+3][lRow]=ra0.w;
            As[nb][lK8+4][lRow]=ra1.x; As[nb][lK8+5][lRow]=ra1.y; As[nb][lK8+6][lRow]=ra1.z; As[nb][lK8+7][lRow]=ra1.w;
            *(float4*)&Bs[nb][vRow][vCol8]     = rb0;
            *(float4*)&Bs[nb][vRow][vCol8 + 4] = rb1;
            __syncthreads();
            buf = nb;
        }
    }

    #pragma unroll
    for (int i = 0; i < 8; ++i) {
        const int row = i0 + ty * 8 + i;
        if (row < L) {
            float* orow = out + ((size_t)b * NN_ + row) * DD + d0 + tx * 8;
            float2 v0 = unpack2(acc[i][0]), v1 = unpack2(acc[i][1]);
            float2 v2 = unpack2(acc[i][2]), v3 = unpack2(acc[i][3]);
            *(float4*)(orow)     = make_float4(v0.x, v0.y, v1.x, v1.y);
            *(float4*)(orow + 4) = make_float4(v2.x, v2.y, v3.x, v3.y);
        }
    }
}

// ---------------------------------------------------------------------------
// Kernel 5a: partial column sums of V (8 segments of 256 rows each).
// ---------------------------------------------------------------------------
__global__ __launch_bounds__(128)
void vmean_part()
{
    const int b   = blockIdx.y;
    const int seg = blockIdx.z;
    const int d   = blockIdx.x * 128 + threadIdx.x;
    const float* v = g_v + (size_t)b * NN_ * DD + (size_t)seg * 256 * DD + d;
    float s0 = 0.f, s1 = 0.f, s2 = 0.f, s3 = 0.f;
    for (int n = 0; n < 256; n += 4) {
        s0 += v[(size_t)(n + 0) * DD];
        s1 += v[(size_t)(n + 1) * DD];
        s2 += v[(size_t)(n + 2) * DD];
        s3 += v[(size_t)(n + 3) * DD];
    }
    g_vpart[((size_t)b * 8 + seg) * DD + d] = (s0 + s1) + (s2 + s3);
}

// ---------------------------------------------------------------------------
// Kernel 5b: rows i >= L get the mean over ALL 2048 V rows.
// ---------------------------------------------------------------------------
__global__ __launch_bounds__(256)
void fill_tail(const int* __restrict__ lens, float* __restrict__ out)
{
    const int b  = blockIdx.y;
    const int L  = get_len(lens, b);
    const int i0 = blockIdx.x * 128;
    const int iStart = (i0 > L) ? i0 : L;
    const int iEnd   = (i0 + 128 < NN_) ? (i0 + 128) : NN_;
    if (iStart >= iEnd) return;

    __shared__ __align__(16) float mean[DD];
    const int tid = threadIdx.x;
    for (int d = tid; d < DD; d += 256) {
        float s = 0.f;
        #pragma unroll
        for (int z = 0; z < 8; ++z) s += g_vpart[((size_t)b * 8 + z) * DD + d];
        mean[d] = s * (1.0f / (float)NN_);
    }
    __syncthreads();

    const int nRows = iEnd - iStart;
    for (int lin = tid; lin < nRows * 128; lin += 256) {
        const int r  = iStart + (lin >> 7);
        const int c4 = (lin & 127);
        const float4 m = *(const float4*)&mean[c4 * 4];
        *(float4*)&out[((size_t)b * NN_ + r) * DD + (size_t)c4 * 4] = m;
    }
}

// ---------------------------------------------------------------------------
extern "C" void kernel_launch(void* const* d_in, const int* in_sizes, int n_in,
                              void* d_out, int out_size)
{
    const float* x    = (const float*)d_in[0];
    const int*   lens = (const int*)d_in[1];   // int32 or int64 — decoded in-kernel
    const float* Wq   = (const float*)d_in[2];
    const float* bq   = (const float*)d_in[3];
    const float* Wk   = (const float*)d_in[4];
    const float* bk   = (const float*)d_in[5];
    const float* Wv   = (const float*)d_in[6];
    const float* bv   = (const float*)d_in[7];
    float* out = (float*)d_out;

    qkv_gemm<<<dim3(128, 4, 3), 256>>>(x, Wq, bq, Wk, bk, Wv, bv);
    score_gemm<<<dim3(16, 16, 8), 256>>>(lens);
    zero_pad<<<dim3(16, 8), 256>>>(lens);
    softmax_kernel<<<dim3(2048, 8), 256>>>(lens);
    out_gemm<<<dim3(16, 4, 8), 256>>>(lens, out);
    vmean_part<<<dim3(4, 8, 8), 128>>>();
    fill_tail<<<dim3(16, 8), 256>>>(lens, out);
}

// round 8
// speedup vs baseline: 1.1627x; 1.0026x over previous
#include <cuda_runtime.h>
#include <math.h>

// Problem constants
#define BB 8
#define NN_ 2048
#define DD 512

static const float SCALE = 0.044194173824159216f; // 1/sqrt(512)

typedef unsigned long long ull;

// Scratch (device globals: allocation-free per harness rules)
__device__ float g_q[(size_t)BB * NN_ * DD];          // 32 MB
__device__ float g_k[(size_t)BB * NN_ * DD];          // 32 MB
__device__ float g_v[(size_t)BB * NN_ * DD];          // 32 MB
__device__ float g_p[(size_t)BB * NN_ * NN_];         // 128 MB scores/probs
__device__ float g_vpart[(size_t)BB * 8 * DD];        // partial V column sums

// ---------------------------------------------------------------------------
// Packed fp32x2 helpers (Blackwell FFMA2 — only reachable via PTX f32x2 ops).
// Numerics identical to two scalar fmaf.
// ---------------------------------------------------------------------------
__device__ __forceinline__ void fma2(ull& d, ull a, ull b)
{
    asm("fma.rn.f32x2 %0, %1, %2, %0;" : "+l"(d) : "l"(a), "l"(b));
}
__device__ __forceinline__ ull pdup(float a)
{
    ull d; unsigned ai = __float_as_uint(a);
    asm("mov.b64 %0, {%1, %1};" : "=l"(d) : "r"(ai));
    return d;
}
__device__ __forceinline__ float2 unpack2(ull p)
{
    unsigned lo, hi;
    asm("mov.b64 {%0, %1}, %2;" : "=r"(lo), "=r"(hi) : "l"(p));
    float2 r; r.x = __uint_as_float(lo); r.y = __uint_as_float(hi);
    return r;
}

// ---------------------------------------------------------------------------
// Dtype-agnostic event_lengths decoder (int64 vs int32 materialization).
// ---------------------------------------------------------------------------
__device__ __forceinline__ int get_len(const int* __restrict__ w, int b)
{
    return (w[1] == 0) ? w[2 * b] : w[b];
}

// ---------------------------------------------------------------------------
// Shared inner product step: 8x8 microtile as 8x4 packed f32x2 FMAs.
// ---------------------------------------------------------------------------
#define MICRO_K_STEP(AsB, BsB, k)                                              \
    {                                                                          \
        const float4* pa = (const float4*)&AsB[k][ty * 8];                     \
        float4 av0 = pa[0], av1 = pa[1];                                       \
        const ulonglong2* pb = (const ulonglong2*)&BsB[k][tx * 8];             \
        ulonglong2 bq0 = pb[0], bq1 = pb[1];                                   \
        ull a2[8];                                                             \
        a2[0] = pdup(av0.x); a2[1] = pdup(av0.y);                              \
        a2[2] = pdup(av0.z); a2[3] = pdup(av0.w);                              \
        a2[4] = pdup(av1.x); a2[5] = pdup(av1.y);                              \
        a2[6] = pdup(av1.z); a2[7] = pdup(av1.w);                              \
        ull b2_0 = bq0.x, b2_1 = bq0.y, b2_2 = bq1.x, b2_3 = bq1.y;            \
        _Pragma("unroll")                                                      \
        for (int i = 0; i < 8; ++i) {                                          \
            fma2(acc[i][0], a2[i], b2_0);                                      \
            fma2(acc[i][1], a2[i], b2_1);                                      \
            fma2(acc[i][2], a2[i], b2_2);                                      \
            fma2(acc[i][3], a2[i], b2_3);                                      \
        }                                                                      \
    }

// ---------------------------------------------------------------------------
// Kernel 1: fused QKV projection (NT GEMM M=16384, N=512, K=512).
// 128x128 tile, BK=16, double-buffered smem, f32x2 FMAs.
// ---------------------------------------------------------------------------
__global__ __launch_bounds__(256, 2)
void qkv_gemm(const float* __restrict__ x,
              const float* __restrict__ Wq, const float* __restrict__ bq,
              const float* __restrict__ Wk, const float* __restrict__ bk,
              const float* __restrict__ Wv, const float* __restrict__ bv)
{
    const int mat = blockIdx.z;
    const float* __restrict__ W    = (mat == 0) ? Wq : (mat == 1) ? Wk : Wv;
    const float* __restrict__ bias = (mat == 0) ? bq : (mat == 1) ? bk : bv;
    float* out = (mat == 0) ? g_q : (mat == 1) ? g_k : g_v;

    __shared__ __align__(16) float As[2][16][128];
    __shared__ __align__(16) float Bs[2][16][128];

    const int tid = threadIdx.x;
    const int tx = tid & 15, ty = tid >> 4;
    const int m0 = blockIdx.x * 128, e0 = blockIdx.y * 128;
    const int lRow = tid >> 1, lK8 = (tid & 1) * 8;

    const float* aP = x + (size_t)(m0 + lRow) * DD + lK8;
    const float* bP = W + (size_t)(e0 + lRow) * DD + lK8;

    // Prologue: tile 0
    float4 ra0 = *(const float4*)(aP),     ra1 = *(const float4*)(aP + 4);
    float4 rb0 = *(const float4*)(bP),     rb1 = *(const float4*)(bP + 4);
    As[0][lK8+0][lRow]=ra0.x; As[0][lK8+1][lRow]=ra0.y; As[0][lK8+2][lRow]=ra0.z; As[0][lK8+3][lRow]=ra0.w;
    As[0][lK8+4][lRow]=ra1.x; As[0][lK8+5][lRow]=ra1.y; As[0][lK8+6][lRow]=ra1.z; As[0][lK8+7][lRow]=ra1.w;
    Bs[0][lK8+0][lRow]=rb0.x; Bs[0][lK8+1][lRow]=rb0.y; Bs[0][lK8+2][lRow]=rb0.z; Bs[0][lK8+3][lRow]=rb0.w;
    Bs[0][lK8+4][lRow]=rb1.x; Bs[0][lK8+5][lRow]=rb1.y; Bs[0][lK8+6][lRow]=rb1.z; Bs[0][lK8+7][lRow]=rb1.w;
    __syncthreads();

    ull acc[8][4];
    #pragma unroll
    for (int i = 0; i < 8; ++i)
        #pragma unroll
        for (int j = 0; j < 4; ++j) acc[i][j] = 0ULL;

    int buf = 0;
    const int T = DD / 16; // 32
    #pragma unroll 1
    for (int t = 0; t < T; ++t) {
        if (t + 1 < T) {
            ra0 = *(const float4*)(aP + (t + 1) * 16);
            ra1 = *(const float4*)(aP + (t + 1) * 16 + 4);
            rb0 = *(const float4*)(bP + (t + 1) * 16);
            rb1 = *(const float4*)(bP + (t + 1) * 16 + 4);
        }
        #pragma unroll
        for (int k = 0; k < 16; ++k) MICRO_K_STEP(As[buf], Bs[buf], k);
        if (t + 1 < T) {
            const int nb = buf ^ 1;
            As[nb][lK8+0][lRow]=ra0.x; As[nb][lK8+1][lRow]=ra0.y; As[nb][lK8+2][lRow]=ra0.z; As[nb][lK8+3][lRow]=ra0.w;
            As[nb][lK8+4][lRow]=ra1.x; As[nb][lK8+5][lRow]=ra1.y; As[nb][lK8+6][lRow]=ra1.z; As[nb][lK8+7][lRow]=ra1.w;
            Bs[nb][lK8+0][lRow]=rb0.x; Bs[nb][lK8+1][lRow]=rb0.y; Bs[nb][lK8+2][lRow]=rb0.z; Bs[nb][lK8+3][lRow]=rb0.w;
            Bs[nb][lK8+4][lRow]=rb1.x; Bs[nb][lK8+5][lRow]=rb1.y; Bs[nb][lK8+6][lRow]=rb1.z; Bs[nb][lK8+7][lRow]=rb1.w;
            __syncthreads();
            buf = nb;
        }
    }

    float bb[8];
    #pragma unroll
    for (int j = 0; j < 8; ++j) bb[j] = bias[e0 + tx * 8 + j];

    #pragma unroll
    for (int i = 0; i < 8; ++i) {
        const int row = m0 + ty * 8 + i;
        float* orow = out + (size_t)row * DD + e0 + tx * 8;
        float2 v0 = unpack2(acc[i][0]), v1 = unpack2(acc[i][1]);
        float2 v2 = unpack2(acc[i][2]), v3 = unpack2(acc[i][3]);
        *(float4*)(orow)     = make_float4(v0.x + bb[0], v0.y + bb[1], v1.x + bb[2], v1.y + bb[3]);
        *(float4*)(orow + 4) = make_float4(v2.x + bb[4], v2.y + bb[5], v3.x + bb[6], v3.y + bb[7]);
    }
}

// ---------------------------------------------------------------------------
// Kernel 2: scores = scale * q @ k^T (NT GEMM K=512), tile-gated on L.
// ---------------------------------------------------------------------------
__global__ __launch_bounds__(256, 2)
void score_gemm(const int* __restrict__ lens)
{
    const int b  = blockIdx.z;
    const int L  = get_len(lens, b);
    const int i0 = blockIdx.x * 128;
    const int j0 = blockIdx.y * 128;
    if (i0 >= L || j0 >= L) return;

    const float* __restrict__ q  = g_q + (size_t)b * NN_ * DD;
    const float* __restrict__ kk = g_k + (size_t)b * NN_ * DD;
    float* p = g_p + (size_t)b * NN_ * NN_;

    __shared__ __align__(16) float As[2][16][128];
    __shared__ __align__(16) float Bs[2][16][128];

    const int tid = threadIdx.x;
    const int tx = tid & 15, ty = tid >> 4;
    const int lRow = tid >> 1, lK8 = (tid & 1) * 8;

    const float* aP = q  + (size_t)(i0 + lRow) * DD + lK8;
    const float* bP = kk + (size_t)(j0 + lRow) * DD + lK8;

    float4 ra0 = *(const float4*)(aP),     ra1 = *(const float4*)(aP + 4);
    float4 rb0 = *(const float4*)(bP),     rb1 = *(const float4*)(bP + 4);
    As[0][lK8+0][lRow]=ra0.x; As[0][lK8+1][lRow]=ra0.y; As[0][lK8+2][lRow]=ra0.z; As[0][lK8+3][lRow]=ra0.w;
    As[0][lK8+4][lRow]=ra1.x; As[0][lK8+5][lRow]=ra1.y; As[0][lK8+6][lRow]=ra1.z; As[0][lK8+7][lRow]=ra1.w;
    Bs[0][lK8+0][lRow]=rb0.x; Bs[0][lK8+1][lRow]=rb0.y; Bs[0][lK8+2][lRow]=rb0.z; Bs[0][lK8+3][lRow]=rb0.w;
    Bs[0][lK8+4][lRow]=rb1.x; Bs[0][lK8+5][lRow]=rb1.y; Bs[0][lK8+6][lRow]=rb1.z; Bs[0][lK8+7][lRow]=rb1.w;
    __syncthreads();

    ull acc[8][4];
    #pragma unroll
    for (int i = 0; i < 8; ++i)
        #pragma unroll
        for (int j = 0; j < 4; ++j) acc[i][j] = 0ULL;

    int buf = 0;
    const int T = DD / 16;
    #pragma unroll 1
    for (int t = 0; t < T; ++t) {
        if (t + 1 < T) {
            ra0 = *(const float4*)(aP + (t + 1) * 16);
            ra1 = *(const float4*)(aP + (t + 1) * 16 + 4);
            rb0 = *(const float4*)(bP + (t + 1) * 16);
            rb1 = *(const float4*)(bP + (t + 1) * 16 + 4);
        }
        #pragma unroll
        for (int k = 0; k < 16; ++k) MICRO_K_STEP(As[buf], Bs[buf], k);
        if (t + 1 < T) {
            const int nb = buf ^ 1;
            As[nb][lK8+0][lRow]=ra0.x; As[nb][lK8+1][lRow]=ra0.y; As[nb][lK8+2][lRow]=ra0.z; As[nb][lK8+3][lRow]=ra0.w;
            As[nb][lK8+4][lRow]=ra1.x; As[nb][lK8+5][lRow]=ra1.y; As[nb][lK8+6][lRow]=ra1.z; As[nb][lK8+7][lRow]=ra1.w;
            Bs[nb][lK8+0][lRow]=rb0.x; Bs[nb][lK8+1][lRow]=rb0.y; Bs[nb][lK8+2][lRow]=rb0.z; Bs[nb][lK8+3][lRow]=rb0.w;
            Bs[nb][lK8+4][lRow]=rb1.x; Bs[nb][lK8+5][lRow]=rb1.y; Bs[nb][lK8+6][lRow]=rb1.z; Bs[nb][lK8+7][lRow]=rb1.w;
            __syncthreads();
            buf = nb;
        }
    }

    #pragma unroll
    for (int i = 0; i < 8; ++i) {
        const int row = i0 + ty * 8 + i;
        float* prow = p + (size_t)row * NN_ + j0 + tx * 8;
        float2 v0 = unpack2(acc[i][0]), v1 = unpack2(acc[i][1]);
        float2 v2 = unpack2(acc[i][2]), v3 = unpack2(acc[i][3]);
        *(float4*)(prow)     = make_float4(v0.x * SCALE, v0.y * SCALE, v1.x * SCALE, v1.y * SCALE);
        *(float4*)(prow + 4) = make_float4(v2.x * SCALE, v2.y * SCALE, v3.x * SCALE, v3.y * SCALE);
    }
}

// ---------------------------------------------------------------------------
// Kernel 2b: zero the prob strip cols [L, ceil16(L)) for rows < L, so
// out_gemm can run fully unpredicated over k < ceil16(L)  (p=0 kills v).
// ---------------------------------------------------------------------------
__global__ __launch_bounds__(256)
void zero_pad(const int* __restrict__ lens)
{
    const int b = blockIdx.y;
    const int L = get_len(lens, b);
    const int Lc = (L + 15) & ~15;
    const int w = Lc - L;
    if (w == 0) return;
    float* p = g_p + (size_t)b * NN_ * NN_;
    const int i0 = blockIdx.x * 128;
    for (int idx = threadIdx.x; idx < 128 * w; idx += 256) {
        const int r = i0 + idx / w;
        const int c = L + idx % w;
        if (r < L) p[(size_t)r * NN_ + c] = 0.f;
    }
}

// ---------------------------------------------------------------------------
// Kernel 3: row softmax over keys j<L, in place.
// ---------------------------------------------------------------------------
__device__ __forceinline__ float blockReduceMax(float v, float* red)
{
    #pragma unroll
    for (int o = 16; o; o >>= 1) v = fmaxf(v, __shfl_xor_sync(0xffffffffu, v, o));
    const int tid = threadIdx.x;
    if ((tid & 31) == 0) red[tid >> 5] = v;
    __syncthreads();
    float r = red[0];
    #pragma unroll
    for (int w = 1; w < 8; ++w) r = fmaxf(r, red[w]);
    __syncthreads();
    return r;
}

__device__ __forceinline__ float blockReduceSum(float v, float* red)
{
    #pragma unroll
    for (int o = 16; o; o >>= 1) v += __shfl_xor_sync(0xffffffffu, v, o);
    const int tid = threadIdx.x;
    if ((tid & 31) == 0) red[tid >> 5] = v;
    __syncthreads();
    float r = red[0];
    #pragma unroll
    for (int w = 1; w < 8; ++w) r += red[w];
    __syncthreads();
    return r;
}

__global__ __launch_bounds__(256)
void softmax_kernel(const int* __restrict__ lens)
{
    const int b = blockIdx.y;
    const int i = blockIdx.x;
    const int L = get_len(lens, b);
    if (i >= L) return;

    float* row = g_p + (size_t)b * NN_ * NN_ + (size_t)i * NN_;
    const int tid = threadIdx.x;
    __shared__ float red[8];

    float mx = -3.0e38f;
    for (int j = tid; j < L; j += 256) mx = fmaxf(mx, row[j]);
    mx = blockReduceMax(mx, red);

    float s = 0.f;
    for (int j = tid; j < L; j += 256) {
        float e = __expf(row[j] - mx);
        row[j] = e;
        s += e;
    }
    s = blockReduceSum(s, red);
    const float inv = 1.0f / s;

    for (int j = tid; j < L; j += 256) row[j] *= inv;
}

// ---------------------------------------------------------------------------
// Kernel 4: out = P @ V (NN GEMM, K = ceil16(L), fully unpredicated loads —
// the zero strip guarantees p=0 for k in [L, ceil16(L))).
// ---------------------------------------------------------------------------
__global__ __launch_bounds__(256, 2)
void out_gemm(const int* __restrict__ lens, float* __restrict__ out)
{
    const int b  = blockIdx.z;
    const int L  = get_len(lens, b);
    const int i0 = blockIdx.x * 128;
    if (i0 >= L) return;
    const int d0 = blockIdx.y * 128;

    const float* __restrict__ p = g_p + (size_t)b * NN_ * NN_;
    const float* __restrict__ v = g_v + (size_t)b * NN_ * DD;

    __shared__ __align__(16) float As[2][16][128];
    __shared__ __align__(16) float Bs[2][16][128];

    const int tid = threadIdx.x;
    const int tx = tid & 15, ty = tid >> 4;
    const int lRow = tid >> 1, lK8 = (tid & 1) * 8;      // A (P) staging
    const int vRow = tid >> 4, vCol8 = (tid & 15) * 8;   // B (V) staging

    const float* aP = p + (size_t)(i0 + lRow) * NN_ + lK8;
    const float* bP = v + (size_t)vRow * DD + d0 + vCol8;

    const int T = (L + 15) >> 4;

    float4 ra0 = *(const float4*)(aP),     ra1 = *(const float4*)(aP + 4);
    float4 rb0 = *(const float4*)(bP),     rb1 = *(const float4*)(bP + 4);
    As[0][lK8+0][lRow]=ra0.x; As[0][lK8+1][lRow]=ra0.y; As[0][lK8+2][lRow]=ra0.z; As[0][lK8+3][lRow]=ra0.w;
    As[0][lK8+4][lRow]=ra1.x; As[0][lK8+5][lRow]=ra1.y; As[0][lK8+6][lRow]=ra1.z; As[0][lK8+7][lRow]=ra1.w;
    *(float4*)&Bs[0][vRow][vCol8]     = rb0;
    *(float4*)&Bs[0][vRow][vCol8 + 4] = rb1;
    __syncthreads();

    ull acc[8][4];
    #pragma unroll
    for (int i = 0; i < 8; ++i)
        #pragma unroll
        for (int j = 0; j < 4; ++j) acc[i][j] = 0ULL;

    int buf = 0;
    #pragma unroll 1
    for (int t = 0; t < T; ++t) {
        if (t + 1 < T) {
            ra0 = *(const float4*)(aP + (t + 1) * 16);
            ra1 = *(const float4*)(aP + (t + 1) * 16 + 4);
            rb0 = *(const float4*)(bP + (size_t)(t + 1) * 16 * DD);
            rb1 = *(const float4*)(bP + (size_t)(t + 1) * 16 * DD + 4);
        }
        #pragma unroll
        for (int k = 0; k < 16; ++k) MICRO_K_STEP(As[buf], Bs[buf], k);
        if (t + 1 < T) {
            const int nb = buf ^ 1;
            As[nb][lK8+0][lRow]=ra0.x; As[nb][lK8+1][lRow]=ra0.y; As[nb][lK8+2][lRow]=ra0.z; As[nb][lK8+3][lRow]=ra0.w;
            As[nb][lK8+4][lRow]=ra1.x; As[nb][lK8+5][lRow]=ra1.y; As[nb][lK8+6][lRow]=ra1.z; As[nb][lK8+7][lRow]=ra1.w;
            *(float4*)&Bs[nb][vRow][vCol8]     = rb0;
            *(float4*)&Bs[nb][vRow][vCol8 + 4] = rb1;
            __syncthreads();
            buf = nb;
        }
    }

    #pragma unroll
    for (int i = 0; i < 8; ++i) {
        const int row = i0 + ty * 8 + i;
        if (row < L) {
            float* orow = out + ((size_t)b * NN_ + row) * DD + d0 + tx * 8;
            float2 v0 = unpack2(acc[i][0]), v1 = unpack2(acc[i][1]);
            float2 v2 = unpack2(acc[i][2]), v3 = unpack2(acc[i][3]);
            *(float4*)(orow)     = make_float4(v0.x, v0.y, v1.x, v1.y);
            *(float4*)(orow + 4) = make_float4(v2.x, v2.y, v3.x, v3.y);
        }
    }
}

// ---------------------------------------------------------------------------
// Kernel 5a: partial column sums of V (8 segments of 256 rows each).
// ---------------------------------------------------------------------------
__global__ __launch_bounds__(128)
void vmean_part()
{
    const int b   = blockIdx.y;
    const int seg = blockIdx.z;
    const int d   = blockIdx.x * 128 + threadIdx.x;
    const float* v = g_v + (size_t)b * NN_ * DD + (size_t)seg * 256 * DD + d;
    float s0 = 0.f, s1 = 0.f, s2 = 0.f, s3 = 0.f;
    for (int n = 0; n < 256; n += 4) {
        s0 += v[(size_t)(n + 0) * DD];
        s1 += v[(size_t)(n + 1) * DD];
        s2 += v[(size_t)(n + 2) * DD];
        s3 += v[(size_t)(n + 3) * DD];
    }
    g_vpart[((size_t)b * 8 + seg) * DD + d] = (s0 + s1) + (s2 + s3);
}

// ---------------------------------------------------------------------------
// Kernel 5b: rows i >= L get the mean over ALL 2048 V rows.
// ---------------------------------------------------------------------------
__global__ __launch_bounds__(256)
void fill_tail(const int* __restrict__ lens, float* __restrict__ out)
{
    const int b  = blockIdx.y;
    const int L  = get_len(lens, b);
    const int i0 = blockIdx.x * 128;
    const int iStart = (i0 > L) ? i0 : L;
    const int iEnd   = (i0 + 128 < NN_) ? (i0 + 128) : NN_;
    if (iStart >= iEnd) return;

    __shared__ __align__(16) float mean[DD];
    const int tid = threadIdx.x;
    for (int d = tid; d < DD; d += 256) {
        float s = 0.f;
        #pragma unroll
        for (int z = 0; z < 8; ++z) s += g_vpart[((size_t)b * 8 + z) * DD + d];
        mean[d] = s * (1.0f / (float)NN_);
    }
    __syncthreads();

    const int nRows = iEnd - iStart;
    for (int lin = tid; lin < nRows * 128; lin += 256) {
        const int r  = iStart + (lin >> 7);
        const int c4 = (lin & 127);
        const float4 m = *(const float4*)&mean[c4 * 4];
        *(float4*)&out[((size_t)b * NN_ + r) * DD + (size_t)c4 * 4] = m;
    }
}

// ---------------------------------------------------------------------------
extern "C" void kernel_launch(void* const* d_in, const int* in_sizes, int n_in,
                              void* d_out, int out_size)
{
    const float* x    = (const float*)d_in[0];
    const int*   lens = (const int*)d_in[1];   // int32 or int64 — decoded in-kernel
    const float* Wq   = (const float*)d_in[2];
    const float* bq   = (const float*)d_in[3];
    const float* Wk   = (const float*)d_in[4];
    const float* bk   = (const float*)d_in[5];
    const float* Wv   = (const float*)d_in[6];
    const float* bv   = (const float*)d_in[7];
    float* out = (float*)d_out;

    qkv_gemm<<<dim3(128, 4, 3), 256>>>(x, Wq, bq, Wk, bk, Wv, bv);
    score_gemm<<<dim3(16, 16, 8), 256>>>(lens);
    zero_pad<<<dim3(16, 8), 256>>>(lens);
    softmax_kernel<<<dim3(2048, 8), 256>>>(lens);
    out_gemm<<<dim3(16, 4, 8), 256>>>(lens, out);
    vmean_part<<<dim3(4, 8, 8), 128>>>();
    fill_tail<<<dim3(16, 8), 256>>>(lens, out);
}

// round 9
// speedup vs baseline: 1.1642x; 1.0013x over previous
#include <cuda_runtime.h>
#include <math.h>

// Problem constants
#define BB 8
#define NN_ 2048
#define DD 512

static const float SCALE = 0.044194173824159216f; // 1/sqrt(512)

typedef unsigned long long ull;

// Scratch (device globals: allocation-free per harness rules)
__device__ float g_q[(size_t)BB * NN_ * DD];          // 32 MB
__device__ float g_k[(size_t)BB * NN_ * DD];          // 32 MB
__device__ float g_v[(size_t)BB * NN_ * DD];          // 32 MB
__device__ float g_p[(size_t)BB * NN_ * NN_];         // 128 MB scores/probs
__device__ float g_vpart[(size_t)BB * 8 * DD];        // partial V column sums

// ---------------------------------------------------------------------------
// Packed fp32x2 helpers (Blackwell FFMA2 — only reachable via PTX f32x2 ops).
// Numerics identical to two scalar fmaf.
// ---------------------------------------------------------------------------
__device__ __forceinline__ void fma2(ull& d, ull a, ull b)
{
    asm("fma.rn.f32x2 %0, %1, %2, %0;" : "+l"(d) : "l"(a), "l"(b));
}
__device__ __forceinline__ ull pdup(float a)
{
    ull d; unsigned ai = __float_as_uint(a);
    asm("mov.b64 %0, {%1, %1};" : "=l"(d) : "r"(ai));
    return d;
}
__device__ __forceinline__ float2 unpack2(ull p)
{
    unsigned lo, hi;
    asm("mov.b64 {%0, %1}, %2;" : "=r"(lo), "=r"(hi) : "l"(p));
    float2 r; r.x = __uint_as_float(lo); r.y = __uint_as_float(hi);
    return r;
}

// ---------------------------------------------------------------------------
// Dtype-agnostic event_lengths decoder (int64 vs int32 materialization).
// ---------------------------------------------------------------------------
__device__ __forceinline__ int get_len(const int* __restrict__ w, int b)
{
    return (w[1] == 0) ? w[2 * b] : w[b];
}

// ---------------------------------------------------------------------------
// Shared inner product step: 8x8 microtile as 8x4 packed f32x2 FMAs.
// ---------------------------------------------------------------------------
#define MICRO_K_STEP(AsB, BsB, k)                                              \
    {                                                                          \
        const float4* pa = (const float4*)&AsB[k][ty * 8];                     \
        float4 av0 = pa[0], av1 = pa[1];                                       \
        const ulonglong2* pb = (const ulonglong2*)&BsB[k][tx * 8];             \
        ulonglong2 bq0 = pb[0], bq1 = pb[1];                                   \
        ull a2[8];                                                             \
        a2[0] = pdup(av0.x); a2[1] = pdup(av0.y);                              \
        a2[2] = pdup(av0.z); a2[3] = pdup(av0.w);                              \
        a2[4] = pdup(av1.x); a2[5] = pdup(av1.y);                              \
        a2[6] = pdup(av1.z); a2[7] = pdup(av1.w);                              \
        ull b2_0 = bq0.x, b2_1 = bq0.y, b2_2 = bq1.x, b2_3 = bq1.y;            \
        _Pragma("unroll")                                                      \
        for (int i = 0; i < 8; ++i) {                                          \
            fma2(acc[i][0], a2[i], b2_0);                                      \
            fma2(acc[i][1], a2[i], b2_1);                                      \
            fma2(acc[i][2], a2[i], b2_2);                                      \
            fma2(acc[i][3], a2[i], b2_3);                                      \
        }                                                                      \
    }

// ---------------------------------------------------------------------------
// Kernel 1: fused QKV projection (NT GEMM M=16384, N=512, K=512).
// 128x128 tile, BK=16, double-buffered smem, f32x2 FMAs.
// ---------------------------------------------------------------------------
__global__ __launch_bounds__(256, 2)
void qkv_gemm(const float* __restrict__ x,
              const float* __restrict__ Wq, const float* __restrict__ bq,
              const float* __restrict__ Wk, const float* __restrict__ bk,
              const float* __restrict__ Wv, const float* __restrict__ bv)
{
    const int mat = blockIdx.z;
    const float* __restrict__ W    = (mat == 0) ? Wq : (mat == 1) ? Wk : Wv;
    const float* __restrict__ bias = (mat == 0) ? bq : (mat == 1) ? bk : bv;
    float* out = (mat == 0) ? g_q : (mat == 1) ? g_k : g_v;

    __shared__ __align__(16) float As[2][16][128];
    __shared__ __align__(16) float Bs[2][16][128];

    const int tid = threadIdx.x;
    const int tx = tid & 15, ty = tid >> 4;
    const int m0 = blockIdx.x * 128, e0 = blockIdx.y * 128;
    const int lRow = tid >> 1, lK8 = (tid & 1) * 8;

    const float* aP = x + (size_t)(m0 + lRow) * DD + lK8;
    const float* bP = W + (size_t)(e0 + lRow) * DD + lK8;

    // Prologue: tile 0
    float4 ra0 = *(const float4*)(aP),     ra1 = *(const float4*)(aP + 4);
    float4 rb0 = *(const float4*)(bP),     rb1 = *(const float4*)(bP + 4);
    As[0][lK8+0][lRow]=ra0.x; As[0][lK8+1][lRow]=ra0.y; As[0][lK8+2][lRow]=ra0.z; As[0][lK8+3][lRow]=ra0.w;
    As[0][lK8+4][lRow]=ra1.x; As[0][lK8+5][lRow]=ra1.y; As[0][lK8+6][lRow]=ra1.z; As[0][lK8+7][lRow]=ra1.w;
    Bs[0][lK8+0][lRow]=rb0.x; Bs[0][lK8+1][lRow]=rb0.y; Bs[0][lK8+2][lRow]=rb0.z; Bs[0][lK8+3][lRow]=rb0.w;
    Bs[0][lK8+4][lRow]=rb1.x; Bs[0][lK8+5][lRow]=rb1.y; Bs[0][lK8+6][lRow]=rb1.z; Bs[0][lK8+7][lRow]=rb1.w;
    __syncthreads();

    ull acc[8][4];
    #pragma unroll
    for (int i = 0; i < 8; ++i)
        #pragma unroll
        for (int j = 0; j < 4; ++j) acc[i][j] = 0ULL;

    int buf = 0;
    const int T = DD / 16; // 32
    #pragma unroll 1
    for (int t = 0; t < T; ++t) {
        if (t + 1 < T) {
            ra0 = *(const float4*)(aP + (t + 1) * 16);
            ra1 = *(const float4*)(aP + (t + 1) * 16 + 4);
            rb0 = *(const float4*)(bP + (t + 1) * 16);
            rb1 = *(const float4*)(bP + (t + 1) * 16 + 4);
        }
        #pragma unroll
        for (int k = 0; k < 16; ++k) MICRO_K_STEP(As[buf], Bs[buf], k);
        if (t + 1 < T) {
            const int nb = buf ^ 1;
            As[nb][lK8+0][lRow]=ra0.x; As[nb][lK8+1][lRow]=ra0.y; As[nb][lK8+2][lRow]=ra0.z; As[nb][lK8+3][lRow]=ra0.w;
            As[nb][lK8+4][lRow]=ra1.x; As[nb][lK8+5][lRow]=ra1.y; As[nb][lK8+6][lRow]=ra1.z; As[nb][lK8+7][lRow]=ra1.w;
            Bs[nb][lK8+0][lRow]=rb0.x; Bs[nb][lK8+1][lRow]=rb0.y; Bs[nb][lK8+2][lRow]=rb0.z; Bs[nb][lK8+3][lRow]=rb0.w;
            Bs[nb][lK8+4][lRow]=rb1.x; Bs[nb][lK8+5][lRow]=rb1.y; Bs[nb][lK8+6][lRow]=rb1.z; Bs[nb][lK8+7][lRow]=rb1.w;
            __syncthreads();
            buf = nb;
        }
    }

    float bb[8];
    #pragma unroll
    for (int j = 0; j < 8; ++j) bb[j] = bias[e0 + tx * 8 + j];

    #pragma unroll
    for (int i = 0; i < 8; ++i) {
        const int row = m0 + ty * 8 + i;
        float* orow = out + (size_t)row * DD + e0 + tx * 8;
        float2 v0 = unpack2(acc[i][0]), v1 = unpack2(acc[i][1]);
        float2 v2 = unpack2(acc[i][2]), v3 = unpack2(acc[i][3]);
        *(float4*)(orow)     = make_float4(v0.x + bb[0], v0.y + bb[1], v1.x + bb[2], v1.y + bb[3]);
        *(float4*)(orow + 4) = make_float4(v2.x + bb[4], v2.y + bb[5], v3.x + bb[6], v3.y + bb[7]);
    }
}

// ---------------------------------------------------------------------------
// Kernel 2: scores = scale * q @ k^T (NT GEMM K=512), tile-gated on L.
// ---------------------------------------------------------------------------
__global__ __launch_bounds__(256, 2)
void score_gemm(const int* __restrict__ lens)
{
    const int b  = blockIdx.z;
    const int L  = get_len(lens, b);
    const int i0 = blockIdx.x * 128;
    const int j0 = blockIdx.y * 128;
    if (i0 >= L || j0 >= L) return;

    const float* __restrict__ q  = g_q + (size_t)b * NN_ * DD;
    const float* __restrict__ kk = g_k + (size_t)b * NN_ * DD;
    float* p = g_p + (size_t)b * NN_ * NN_;

    __shared__ __align__(16) float As[2][16][128];
    __shared__ __align__(16) float Bs[2][16][128];

    const int tid = threadIdx.x;
    const int tx = tid & 15, ty = tid >> 4;
    const int lRow = tid >> 1, lK8 = (tid & 1) * 8;

    const float* aP = q  + (size_t)(i0 + lRow) * DD + lK8;
    const float* bP = kk + (size_t)(j0 + lRow) * DD + lK8;

    float4 ra0 = *(const float4*)(aP),     ra1 = *(const float4*)(aP + 4);
    float4 rb0 = *(const float4*)(bP),     rb1 = *(const float4*)(bP + 4);
    As[0][lK8+0][lRow]=ra0.x; As[0][lK8+1][lRow]=ra0.y; As[0][lK8+2][lRow]=ra0.z; As[0][lK8+3][lRow]=ra0.w;
    As[0][lK8+4][lRow]=ra1.x; As[0][lK8+5][lRow]=ra1.y; As[0][lK8+6][lRow]=ra1.z; As[0][lK8+7][lRow]=ra1.w;
    Bs[0][lK8+0][lRow]=rb0.x; Bs[0][lK8+1][lRow]=rb0.y; Bs[0][lK8+2][lRow]=rb0.z; Bs[0][lK8+3][lRow]=rb0.w;
    Bs[0][lK8+4][lRow]=rb1.x; Bs[0][lK8+5][lRow]=rb1.y; Bs[0][lK8+6][lRow]=rb1.z; Bs[0][lK8+7][lRow]=rb1.w;
    __syncthreads();

    ull acc[8][4];
    #pragma unroll
    for (int i = 0; i < 8; ++i)
        #pragma unroll
        for (int j = 0; j < 4; ++j) acc[i][j] = 0ULL;

    int buf = 0;
    const int T = DD / 16;
    #pragma unroll 1
    for (int t = 0; t < T; ++t) {
        if (t + 1 < T) {
            ra0 = *(const float4*)(aP + (t + 1) * 16);
            ra1 = *(const float4*)(aP + (t + 1) * 16 + 4);
            rb0 = *(const float4*)(bP + (t + 1) * 16);
            rb1 = *(const float4*)(bP + (t + 1) * 16 + 4);
        }
        #pragma unroll
        for (int k = 0; k < 16; ++k) MICRO_K_STEP(As[buf], Bs[buf], k);
        if (t + 1 < T) {
            const int nb = buf ^ 1;
            As[nb][lK8+0][lRow]=ra0.x; As[nb][lK8+1][lRow]=ra0.y; As[nb][lK8+2][lRow]=ra0.z; As[nb][lK8+3][lRow]=ra0.w;
            As[nb][lK8+4][lRow]=ra1.x; As[nb][lK8+5][lRow]=ra1.y; As[nb][lK8+6][lRow]=ra1.z; As[nb][lK8+7][lRow]=ra1.w;
            Bs[nb][lK8+0][lRow]=rb0.x; Bs[nb][lK8+1][lRow]=rb0.y; Bs[nb][lK8+2][lRow]=rb0.z; Bs[nb][lK8+3][lRow]=rb0.w;
            Bs[nb][lK8+4][lRow]=rb1.x; Bs[nb][lK8+5][lRow]=rb1.y; Bs[nb][lK8+6][lRow]=rb1.z; Bs[nb][lK8+7][lRow]=rb1.w;
            __syncthreads();
            buf = nb;
        }
    }

    #pragma unroll
    for (int i = 0; i < 8; ++i) {
        const int row = i0 + ty * 8 + i;
        float* prow = p + (size_t)row * NN_ + j0 + tx * 8;
        float2 v0 = unpack2(acc[i][0]), v1 = unpack2(acc[i][1]);
        float2 v2 = unpack2(acc[i][2]), v3 = unpack2(acc[i][3]);
        *(float4*)(prow)     = make_float4(v0.x * SCALE, v0.y * SCALE, v1.x * SCALE, v1.y * SCALE);
        *(float4*)(prow + 4) = make_float4(v2.x * SCALE, v2.y * SCALE, v3.x * SCALE, v3.y * SCALE);
    }
}

// ---------------------------------------------------------------------------
// Kernel 2b: zero the prob strip cols [L, ceil16(L)) for rows < L, so
// out_gemm can run fully unpredicated over k < ceil16(L)  (p=0 kills v).
// ---------------------------------------------------------------------------
__global__ __launch_bounds__(256)
void zero_pad(const int* __restrict__ lens)
{
    const int b = blockIdx.y;
    const int L = get_len(lens, b);
    const int Lc = (L + 15) & ~15;
    const int w = Lc - L;
    if (w == 0) return;
    float* p = g_p + (size_t)b * NN_ * NN_;
    const int i0 = blockIdx.x * 128;
    for (int idx = threadIdx.x; idx < 128 * w; idx += 256) {
        const int r = i0 + idx / w;
        const int c = L + idx % w;
        if (r < L) p[(size_t)r * NN_ + c] = 0.f;
    }
}

// ---------------------------------------------------------------------------
// Kernel 3: row softmax over keys j<L, in place.
// ---------------------------------------------------------------------------
__device__ __forceinline__ float blockReduceMax(float v, float* red)
{
    #pragma unroll
    for (int o = 16; o; o >>= 1) v = fmaxf(v, __shfl_xor_sync(0xffffffffu, v, o));
    const int tid = threadIdx.x;
    if ((tid & 31) == 0) red[tid >> 5] = v;
    __syncthreads();
    float r = red[0];
    #pragma unroll
    for (int w = 1; w < 8; ++w) r = fmaxf(r, red[w]);
    __syncthreads();
    return r;
}

__device__ __forceinline__ float blockReduceSum(float v, float* red)
{
    #pragma unroll
    for (int o = 16; o; o >>= 1) v += __shfl_xor_sync(0xffffffffu, v, o);
    const int tid = threadIdx.x;
    if ((tid & 31) == 0) red[tid >> 5] = v;
    __syncthreads();
    float r = red[0];
    #pragma unroll
    for (int w = 1; w < 8; ++w) r += red[w];
    __syncthreads();
    return r;
}

__global__ __launch_bounds__(256)
void softmax_kernel(const int* __restrict__ lens)
{
    const int b = blockIdx.y;
    const int i = blockIdx.x;
    const int L = get_len(lens, b);
    if (i >= L) return;

    float* row = g_p + (size_t)b * NN_ * NN_ + (size_t)i * NN_;
    const int tid = threadIdx.x;
    __shared__ float red[8];

    float mx = -3.0e38f;
    for (int j = tid; j < L; j += 256) mx = fmaxf(mx, row[j]);
    mx = blockReduceMax(mx, red);

    float s = 0.f;
    for (int j = tid; j < L; j += 256) {
        float e = __expf(row[j] - mx);
        row[j] = e;
        s += e;
    }
    s = blockReduceSum(s, red);
    const float inv = 1.0f / s;

    for (int j = tid; j < L; j += 256) row[j] *= inv;
}

// ---------------------------------------------------------------------------
// Kernel 4: out = P @ V (NN GEMM, K = ceil16(L), fully unpredicated loads —
// the zero strip guarantees p=0 for k in [L, ceil16(L))).
// ---------------------------------------------------------------------------
__global__ __launch_bounds__(256, 2)
void out_gemm(const int* __restrict__ lens, float* __restrict__ out)
{
    const int b  = blockIdx.z;
    const int L  = get_len(lens, b);
    const int i0 = blockIdx.x * 128;
    if (i0 >= L) return;
    const int d0 = blockIdx.y * 128;

    const float* __restrict__ p = g_p + (size_t)b * NN_ * NN_;
    const float* __restrict__ v = g_v + (size_t)b * NN_ * DD;

    __shared__ __align__(16) float As[2][16][128];
    __shared__ __align__(16) float Bs[2][16][128];

    const int tid = threadIdx.x;
    const int tx = tid & 15, ty = tid >> 4;
    const int lRow = tid >> 1, lK8 = (tid & 1) * 8;      // A (P) staging
    const int vRow = tid >> 4, vCol8 = (tid & 15) * 8;   // B (V) staging

    const float* aP = p + (size_t)(i0 + lRow) * NN_ + lK8;
    const float* bP = v + (size_t)vRow * DD + d0 + vCol8;

    const int T = (L + 15) >> 4;

    float4 ra0 = *(const float4*)(aP),     ra1 = *(const float4*)(aP + 4);
    float4 rb0 = *(const float4*)(bP),     rb1 = *(const float4*)(bP + 4);
    As[0][lK8+0][lRow]=ra0.x; As[0][lK8+1][lRow]=ra0.y; As[0][lK8+2][lRow]=ra0.z; As[0][lK8+3][lRow]=ra0.w;
    As[0][lK8+4][lRow]=ra1.x; As[0][lK8+5][lRow]=ra1.y; As[0][lK8+6][lRow]=ra1.z; As[0][lK8+7][lRow]=ra1.w;
    *(float4*)&Bs[0][vRow][vCol8]     = rb0;
    *(float4*)&Bs[0][vRow][vCol8 + 4] = rb1;
    __syncthreads();

    ull acc[8][4];
    #pragma unroll
    for (int i = 0; i < 8; ++i)
        #pragma unroll
        for (int j = 0; j < 4; ++j) acc[i][j] = 0ULL;

    int buf = 0;
    #pragma unroll 1
    for (int t = 0; t < T; ++t) {
        if (t + 1 < T) {
            ra0 = *(const float4*)(aP + (t + 1) * 16);
            ra1 = *(const float4*)(aP + (t + 1) * 16 + 4);
            rb0 = *(const float4*)(bP + (size_t)(t + 1) * 16 * DD);
            rb1 = *(const float4*)(bP + (size_t)(t + 1) * 16 * DD + 4);
        }
        #pragma unroll
        for (int k = 0; k < 16; ++k) MICRO_K_STEP(As[buf], Bs[buf], k);
        if (t + 1 < T) {
            const int nb = buf ^ 1;
            As[nb][lK8+0][lRow]=ra0.x; As[nb][lK8+1][lRow]=ra0.y; As[nb][lK8+2][lRow]=ra0.z; As[nb][lK8+3][lRow]=ra0.w;
            As[nb][lK8+4][lRow]=ra1.x; As[nb][lK8+5][lRow]=ra1.y; As[nb][lK8+6][lRow]=ra1.z; As[nb][lK8+7][lRow]=ra1.w;
            *(float4*)&Bs[nb][vRow][vCol8]     = rb0;
            *(float4*)&Bs[nb][vRow][vCol8 + 4] = rb1;
            __syncthreads();
            buf = nb;
        }
    }

    #pragma unroll
    for (int i = 0; i < 8; ++i) {
        const int row = i0 + ty * 8 + i;
        if (row < L) {
            float* orow = out + ((size_t)b * NN_ + row) * DD + d0 + tx * 8;
            float2 v0 = unpack2(acc[i][0]), v1 = unpack2(acc[i][1]);
            float2 v2 = unpack2(acc[i][2]), v3 = unpack2(acc[i][3]);
            *(float4*)(orow)     = make_float4(v0.x, v0.y, v1.x, v1.y);
            *(float4*)(orow + 4) = make_float4(v2.x, v2.y, v3.x, v3.y);
        }
    }
}

// ---------------------------------------------------------------------------
// Kernel 5a: partial column sums of V (8 segments of 256 rows each).
// ---------------------------------------------------------------------------
__global__ __launch_bounds__(128)
void vmean_part()
{
    const int b   = blockIdx.y;
    const int seg = blockIdx.z;
    const int d   = blockIdx.x * 128 + threadIdx.x;
    const float* v = g_v + (size_t)b * NN_ * DD + (size_t)seg * 256 * DD + d;
    float s0 = 0.f, s1 = 0.f, s2 = 0.f, s3 = 0.f;
    for (int n = 0; n < 256; n += 4) {
        s0 += v[(size_t)(n + 0) * DD];
        s1 += v[(size_t)(n + 1) * DD];
        s2 += v[(size_t)(n + 2) * DD];
        s3 += v[(size_t)(n + 3) * DD];
    }
    g_vpart[((size_t)b * 8 + seg) * DD + d] = (s0 + s1) + (s2 + s3);
}

// ---------------------------------------------------------------------------
// Kernel 5b: rows i >= L get the mean over ALL 2048 V rows.
// ---------------------------------------------------------------------------
__global__ __launch_bounds__(256)
void fill_tail(const int* __restrict__ lens, float* __restrict__ out)
{
    const int b  = blockIdx.y;
    const int L  = get_len(lens, b);
    const int i0 = blockIdx.x * 128;
    const int iStart = (i0 > L) ? i0 : L;
    const int iEnd   = (i0 + 128 < NN_) ? (i0 + 128) : NN_;
    if (iStart >= iEnd) return;

    __shared__ __align__(16) float mean[DD];
    const int tid = threadIdx.x;
    for (int d = tid; d < DD; d += 256) {
        float s = 0.f;
        #pragma unroll
        for (int z = 0; z < 8; ++z) s += g_vpart[((size_t)b * 8 + z) * DD + d];
        mean[d] = s * (1.0f / (float)NN_);
    }
    __syncthreads();

    const int nRows = iEnd - iStart;
    for (int lin = tid; lin < nRows * 128; lin += 256) {
        const int r  = iStart + (lin >> 7);
        const int c4 = (lin & 127);
        const float4 m = *(const float4*)&mean[c4 * 4];
        *(float4*)&out[((size_t)b * NN_ + r) * DD + (size_t)c4 * 4] = m;
    }
}

// ---------------------------------------------------------------------------
extern "C" void kernel_launch(void* const* d_in, const int* in_sizes, int n_in,
                              void* d_out, int out_size)
{
    const float* x    = (const float*)d_in[0];
    const int*   lens = (const int*)d_in[1];   // int32 or int64 — decoded in-kernel
    const float* Wq   = (const float*)d_in[2];
    const float* bq   = (const float*)d_in[3];
    const float* Wk   = (const float*)d_in[4];
    const float* bk   = (const float*)d_in[5];
    const float* Wv   = (const float*)d_in[6];
    const float* bv   = (const float*)d_in[7];
    float* out = (float*)d_out;

    qkv_gemm<<<dim3(128, 4, 3), 256>>>(x, Wq, bq, Wk, bk, Wv, bv);
    score_gemm<<<dim3(16, 16, 8), 256>>>(lens);
    zero_pad<<<dim3(16, 8), 256>>>(lens);
    softmax_kernel<<<dim3(2048, 8), 256>>>(lens);
    out_gemm<<<dim3(16, 4, 8), 256>>>(lens, out);
    vmean_part<<<dim3(4, 8, 8), 128>>>();
    fill_tail<<<dim3(16, 8), 256>>>(lens, out);
}